// round 1
// baseline (speedup 1.0000x reference)
#include <cuda_runtime.h>

// Per-edge dot product: out[e] = dot(h[src[e]], h[dst[e]]), D=128 fp32.
// One warp per edge; lane i handles float4 chunk i (32 lanes x 4 floats = 128).
// Index dtype (int32 vs int64) detected at runtime from the bit pattern.

__device__ int g_is_i32;

// If indices are int64 with values < 2^31, every odd int32 word is zero.
// If they are genuine int32 indices, sampled odd words are random node ids
// (any nonzero proves int32). Single block, deterministic, no atomics on
// stale state (flag is overwritten unconditionally every launch).
__global__ void detect_idx_dtype_kernel(const int* __restrict__ s) {
    __shared__ int red[256];
    int t = threadIdx.x;
    int nz = 0;
    #pragma unroll
    for (int i = t; i < 4096; i += 256) nz |= s[2 * i + 1];
    red[t] = nz;
    __syncthreads();
    #pragma unroll
    for (int off = 128; off > 0; off >>= 1) {
        if (t < off) red[t] |= red[t + off];
        __syncthreads();
    }
    if (t == 0) g_is_i32 = (red[0] != 0) ? 1 : 0;
}

__global__ __launch_bounds__(256) void edge_dot_kernel(
    const float* __restrict__ h,
    const void* __restrict__ srcp,
    const void* __restrict__ dstp,
    float* __restrict__ out,
    int n_edges)
{
    int gw   = (int)((blockIdx.x * 256u + threadIdx.x) >> 5);  // global warp = edge id
    int lane = threadIdx.x & 31;
    if (gw >= n_edges) return;

    long long s, d;
    if (g_is_i32) {
        s = ((const int*)srcp)[gw];
        d = ((const int*)dstp)[gw];
    } else {
        s = ((const long long*)srcp)[gw];
        d = ((const long long*)dstp)[gw];
    }

    // Two independent 16B loads per lane -> warp covers 512B per operand,
    // perfectly coalesced (4 x 128B L2 lines each).
    const float4* __restrict__ a4 = (const float4*)(h + s * 128);
    const float4* __restrict__ b4 = (const float4*)(h + d * 128);
    float4 a = a4[lane];
    float4 b = b4[lane];

    float sum = fmaf(a.x, b.x, fmaf(a.y, b.y, fmaf(a.z, b.z, a.w * b.w)));

    #pragma unroll
    for (int off = 16; off > 0; off >>= 1)
        sum += __shfl_xor_sync(0xffffffffu, sum, off);

    if (lane == 0) out[gw] = sum;
}

extern "C" void kernel_launch(void* const* d_in, const int* in_sizes, int n_in,
                              void* d_out, int out_size) {
    const float* h   = (const float*)d_in[0];
    const void*  src = d_in[1];
    const void*  dst = d_in[2];
    float* out = (float*)d_out;

    int n_edges = in_sizes[1];  // element count of src == E

    detect_idx_dtype_kernel<<<1, 256>>>((const int*)src);

    // 32 threads per edge, 256 threads per block -> 8 edges per block
    int blocks = (n_edges + 7) / 8;
    edge_dot_kernel<<<blocks, 256>>>(h, src, dst, out, n_edges);
}

// round 2
// speedup vs baseline: 1.7096x; 1.7096x over previous
#include <cuda_runtime.h>

// Per-edge dot product: out[e] = dot(h[src[e]], h[dst[e]]), D=128 fp32.
// 8 lanes per edge (4 edges per warp). Lane `sub` loads float4 chunks
// sub, sub+8, sub+16, sub+24 of each 512B row: every warp-level LDG.128
// touches exactly 4 full 128B lines (full sector utilization), and each
// thread has 8 independent loads in flight (MLP=8).
// Index dtype (int32 vs int64) detected at runtime from the bit pattern.

__device__ int g_is_i32;

// If indices are int64 with values < 2^31, every odd int32 word is zero.
// Any nonzero odd word proves int32. Overwritten unconditionally each launch.
__global__ void detect_idx_dtype_kernel(const int* __restrict__ s) {
    __shared__ int red[256];
    int t = threadIdx.x;
    int nz = 0;
    #pragma unroll
    for (int i = t; i < 4096; i += 256) nz |= s[2 * i + 1];
    red[t] = nz;
    __syncthreads();
    #pragma unroll
    for (int off = 128; off > 0; off >>= 1) {
        if (t < off) red[t] |= red[t + off];
        __syncthreads();
    }
    if (t == 0) g_is_i32 = (red[0] != 0) ? 1 : 0;
}

__global__ __launch_bounds__(256) void edge_dot_kernel(
    const float* __restrict__ h,
    const void* __restrict__ srcp,
    const void* __restrict__ dstp,
    float* __restrict__ out,
    int n_edges)
{
    int tid = (int)(blockIdx.x * 256u + threadIdx.x);
    int e   = tid >> 3;            // edge id: 8 lanes per edge
    int sub = threadIdx.x & 7;     // lane within octet
    if (e >= n_edges) return;

    long long s, d;
    if (g_is_i32) {
        s = ((const int*)srcp)[e];
        d = ((const int*)dstp)[e];
    } else {
        s = ((const long long*)srcp)[e];
        d = ((const long long*)dstp)[e];
    }

    const float4* __restrict__ a4 = (const float4*)(h + s * 128) + sub;
    const float4* __restrict__ b4 = (const float4*)(h + d * 128) + sub;

    // 8 independent 16B loads issued before any use (MLP=8).
    float4 a0 = a4[0], a1 = a4[8], a2 = a4[16], a3 = a4[24];
    float4 b0 = b4[0], b1 = b4[8], b2 = b4[16], b3 = b4[24];

    float s0 = fmaf(a0.x, b0.x, fmaf(a0.y, b0.y, fmaf(a0.z, b0.z, a0.w * b0.w)));
    float s1 = fmaf(a1.x, b1.x, fmaf(a1.y, b1.y, fmaf(a1.z, b1.z, a1.w * b1.w)));
    float s2 = fmaf(a2.x, b2.x, fmaf(a2.y, b2.y, fmaf(a2.z, b2.z, a2.w * b2.w)));
    float s3 = fmaf(a3.x, b3.x, fmaf(a3.y, b3.y, fmaf(a3.z, b3.z, a3.w * b3.w)));
    float sum = (s0 + s1) + (s2 + s3);

    // Butterfly reduce within the 8-lane octet (3 steps instead of 5).
    sum += __shfl_xor_sync(0xffffffffu, sum, 4);
    sum += __shfl_xor_sync(0xffffffffu, sum, 2);
    sum += __shfl_xor_sync(0xffffffffu, sum, 1);

    if (sub == 0) out[e] = sum;   // 4 consecutive edges per warp -> 16B coalesced
}

extern "C" void kernel_launch(void* const* d_in, const int* in_sizes, int n_in,
                              void* d_out, int out_size) {
    const float* h   = (const float*)d_in[0];
    const void*  src = d_in[1];
    const void*  dst = d_in[2];
    float* out = (float*)d_out;

    int n_edges = in_sizes[1];  // element count of src == E

    detect_idx_dtype_kernel<<<1, 256>>>((const int*)src);

    // 8 threads per edge, 256 threads per block -> 32 edges per block
    int blocks = (n_edges + 31) / 32;
    edge_dot_kernel<<<blocks, 256>>>(h, src, dst, out, n_edges);
}